// round 17
// baseline (speedup 1.0000x reference)
#include <cuda_runtime.h>
#include <cuda_bf16.h>
#include <cstdint>

// ---------------------------------------------------------------------------
// out[n] = (segment_sum(pred_prob[src], dst)[n] - 1)^2 * special_cost[n]
// N = 1,000,000 nodes, E = 16,000,000 edges.
//
// v17: best measured config (2-launch: scatter 2 edges/thread -> apply+reset
// 4 elems/thread) with ONE delta: scatter block size 256 -> 128 (last
// unswept axis; same per-thread instruction mix, 2x CTAs, finer L1tex-queue
// granularity).
//
// FLOOR (R15 profile: L2=82.7% peak, issue=5.7%): scatter is LTS/L2
// sector-bandwidth bound (~1GB sector traffic + 128MB index stream at
// ~6300 B/cyc) ~= 122.5us. Edge-batching U-curve swept: 1->137.5, 2->129.2,
// 4->129.3, 8->135.2. Fusion rejected (+43us, R15). Prefetch neutral (R12).
// ---------------------------------------------------------------------------

#define MAX_NODES 1000000
__device__ float g_accum[MAX_NODES];   // static zero-init

__global__ __launch_bounds__(128) void scatter_accum_kernel(
        const float* __restrict__ pred_prob,
        const int*   __restrict__ src,
        const int*   __restrict__ dst,
        int num_edges) {
    int i = blockIdx.x * blockDim.x + threadIdx.x;
    int base = i * 2;
    if (base + 1 < num_edges) {
        int2 s2 = *reinterpret_cast<const int2*>(src + base);
        int2 d2 = *reinterpret_cast<const int2*>(dst + base);
        float m0 = __ldg(pred_prob + s2.x);
        float m1 = __ldg(pred_prob + s2.y);
        atomicAdd(g_accum + d2.x, m0);   // return unused -> RED
        atomicAdd(g_accum + d2.y, m1);
    } else if (base < num_edges) {
        atomicAdd(g_accum + dst[base], __ldg(pred_prob + src[base]));
    }
}

// Reads accumulated sums, computes (a-1)^2 * cost into out, and resets the
// accumulator to zero so the next (graph-replayed) call starts clean.
__global__ __launch_bounds__(256) void apply_reset_kernel(
        const float* __restrict__ special_cost,
        float*       __restrict__ out,
        int n) {
    int i = blockIdx.x * blockDim.x + threadIdx.x;
    int base = i * 4;
    if (base + 3 < n) {
        float4 a = *reinterpret_cast<const float4*>(g_accum + base);
        float4 c = *reinterpret_cast<const float4*>(special_cost + base);
        float4 r;
        float h;
        h = a.x - 1.0f; r.x = h * h * c.x;
        h = a.y - 1.0f; r.y = h * h * c.y;
        h = a.z - 1.0f; r.z = h * h * c.z;
        h = a.w - 1.0f; r.w = h * h * c.w;
        *reinterpret_cast<float4*>(out + base) = r;
        *reinterpret_cast<float4*>(g_accum + base) =
            make_float4(0.0f, 0.0f, 0.0f, 0.0f);
    } else {
        for (int k = base; k < n; ++k) {
            float h = g_accum[k] - 1.0f;
            out[k] = h * h * special_cost[k];
            g_accum[k] = 0.0f;
        }
    }
}

// Fallback path (N > MAX_NODES): classic init/scatter/apply on d_out.
__global__ __launch_bounds__(256) void init_kernel(float* __restrict__ out, int n) {
    int i = blockIdx.x * blockDim.x + threadIdx.x;
    int base = i * 4;
    if (base + 3 < n) {
        *reinterpret_cast<float4*>(out + base) =
            make_float4(-1.0f, -1.0f, -1.0f, -1.0f);
    } else {
        for (int k = base; k < n; ++k) out[k] = -1.0f;
    }
}

__global__ __launch_bounds__(128) void scatter_out_kernel(
        const float* __restrict__ pred_prob,
        const int*   __restrict__ src,
        const int*   __restrict__ dst,
        float*       __restrict__ out,
        int num_edges) {
    int i = blockIdx.x * blockDim.x + threadIdx.x;
    int base = i * 2;
    if (base + 1 < num_edges) {
        int2 s2 = *reinterpret_cast<const int2*>(src + base);
        int2 d2 = *reinterpret_cast<const int2*>(dst + base);
        atomicAdd(out + d2.x, __ldg(pred_prob + s2.x));
        atomicAdd(out + d2.y, __ldg(pred_prob + s2.y));
    } else if (base < num_edges) {
        atomicAdd(out + dst[base], __ldg(pred_prob + src[base]));
    }
}

__global__ __launch_bounds__(256) void apply_inplace_kernel(
        float* __restrict__ out,
        const float* __restrict__ special_cost,
        int n) {
    int i = blockIdx.x * blockDim.x + threadIdx.x;
    int base = i * 4;
    if (base + 3 < n) {
        float4 h = *reinterpret_cast<const float4*>(out + base);
        float4 c = *reinterpret_cast<const float4*>(special_cost + base);
        h.x = h.x * h.x * c.x;
        h.y = h.y * h.y * c.y;
        h.z = h.z * h.z * c.z;
        h.w = h.w * h.w * c.w;
        *reinterpret_cast<float4*>(out + base) = h;
    } else {
        for (int k = base; k < n; ++k) {
            float h = out[k];
            out[k] = h * h * special_cost[k];
        }
    }
}

extern "C" void kernel_launch(void* const* d_in, const int* in_sizes, int n_in,
                              void* d_out, int out_size) {
    const float* pred_prob    = (const float*)d_in[0];
    const float* special_cost = (const float*)d_in[1];
    const int*   src          = (const int*)d_in[2];
    const int*   dst          = (const int*)d_in[3];
    float*       out          = (float*)d_out;

    const int N = in_sizes[0];
    const int E = in_sizes[2];

    const int sthreads = 128;   // scatter block size (this round's delta)
    const int athreads = 256;
    int eblocks = ((E + 1) / 2 + sthreads - 1) / sthreads;
    int nblocks = ((N + 3) / 4 + athreads - 1) / athreads;

    if (N <= MAX_NODES) {
        scatter_accum_kernel<<<eblocks, sthreads>>>(pred_prob, src, dst, E);
        apply_reset_kernel<<<nblocks, athreads>>>(special_cost, out, N);
    } else {
        init_kernel<<<nblocks, athreads>>>(out, N);
        scatter_out_kernel<<<eblocks, sthreads>>>(pred_prob, src, dst, out, E);
        apply_inplace_kernel<<<nblocks, athreads>>>(out, special_cost, N);
    }
}